// round 7
// baseline (speedup 1.0000x reference)
#include <cuda_runtime.h>
#include <math.h>
#include <stdint.h>

typedef unsigned long long u64;

// ---------------- problem constants ----------------
#define NB   128
#define SSEG 20
#define DDICT 1000
#define LSEG 200
#define OUTDIM 62      // 2 + 3*20

// ---------------- f32x2 helpers ----------------
__device__ __forceinline__ u64 pack2(float a, float b) {
    u64 r; asm("mov.b64 %0, {%1, %2};" : "=l"(r) : "f"(a), "f"(b)); return r;
}
__device__ __forceinline__ u64 fma2(u64 a, u64 b, u64 c) {
    u64 d; asm("fma.rn.f32x2 %0, %1, %2, %3;" : "=l"(d) : "l"(a), "l"(b), "l"(c)); return d;
}
__device__ __forceinline__ void unpack2(u64 v, float& lo, float& hi) {
    asm("mov.b64 {%0, %1}, %2;" : "=f"(lo), "=f"(hi) : "l"(v));
}

// ---------------- scratch (device globals) ----------------
__device__ float g_h1[(size_t)NB*64*49*49];
__device__ float g_h2[(size_t)NB*128*23*23];
__device__ float g_h3[(size_t)NB*256*10*10];
__device__ float g_h4[(size_t)NB*512*4*4];
__device__ float g_a1[NB*2048];
__device__ float g_a2[NB*2048];
__device__ float g_part[2*NB*2048];
__device__ float g_p [NB*OUTDIM];
// Winograd-transformed weights: [cg][ci][j16][c8]
__device__ __align__(16) float g_w1u[(size_t)64*3*16];
__device__ __align__(16) float g_w2u[(size_t)128*64*16];
__device__ __align__(16) float g_w3u[(size_t)256*128*16];
__device__ __align__(16) float g_w4u[(size_t)512*256*16];

// ---------------- Winograd weight transform: U = G g G^T ----------------
// w: [COUT][CIN][3][3]; wu: [cg][ci][16][8]
__global__ void repack_wino(const float* __restrict__ w, float* __restrict__ wu,
                            int CIN, int COUT)
{
    int i = blockIdx.x * blockDim.x + threadIdx.x;
    if (i >= COUT * CIN) return;
    int ci = i % CIN, co = i / CIN;
    const float* g = w + (size_t)(co * CIN + ci) * 9;

    // Gg: 4 rows x 3 cols
    float t[4][3];
    #pragma unroll
    for (int c = 0; c < 3; c++) {
        float g0 = g[0 * 3 + c], g1 = g[1 * 3 + c], g2 = g[2 * 3 + c];
        t[0][c] = g0;
        t[1][c] = 0.5f * (g0 + g1 + g2);
        t[2][c] = 0.5f * (g0 - g1 + g2);
        t[3][c] = g2;
    }
    // U = (Gg) G^T: per row -> 4 cols
    float U[16];
    #pragma unroll
    for (int r = 0; r < 4; r++) {
        float a = t[r][0], b = t[r][1], c = t[r][2];
        U[r * 4 + 0] = a;
        U[r * 4 + 1] = 0.5f * (a + b + c);
        U[r * 4 + 2] = 0.5f * (a - b + c);
        U[r * 4 + 3] = c;
    }
    size_t base = ((size_t)(co >> 3) * CIN + ci) * 128 + (co & 7);
    #pragma unroll
    for (int j = 0; j < 16; j++)
        wu[base + j * 8] = U[j];
}

// ---------------- Winograd F(2x2,3x3) fused conv + bias + maxpool2 + relu ----------------
// Each thread: one pooled output position x 8 consecutive output channels (4 f32x2 pairs).
// The 4x4 input patch IS the Winograd tile; pooled output = max over the 2x2 Y tile.
template<int CIN, int HIN, int WIN, int HP, int WP, int COUT>
__global__ __launch_bounds__(256)
void conv_wino(const float* __restrict__ in,
               const float* __restrict__ wu,    // [cg][ci][16][8]
               const float* __restrict__ bias,
               float* __restrict__ out)
{
    constexpr int COG = COUT / 8;
    int idx = blockIdx.x * blockDim.x + threadIdx.x;
    const int total = NB * COG * HP * WP;
    if (idx >= total) return;

    int pw = idx % WP;  int t2 = idx / WP;
    int ph = t2 % HP;   t2 /= HP;
    int cg = t2 % COG;  t2 /= COG;
    int b  = t2;
    int co0 = cg * 8;

    u64 acc[4][16];
    #pragma unroll
    for (int p = 0; p < 4; p++)
        #pragma unroll
        for (int j = 0; j < 16; j++) acc[p][j] = 0ull;

    const float* inb = in + ((size_t)b * CIN * HIN + 2 * ph) * WIN + 2 * pw;
    const ulonglong2* __restrict__ wbase =
        reinterpret_cast<const ulonglong2*>(wu) + (size_t)cg * CIN * 32;

    for (int ci = 0; ci < CIN; ci++) {
        const float* ip = inb + (size_t)ci * HIN * WIN;
        float xv[16];
        #pragma unroll
        for (int r = 0; r < 4; r++)
            #pragma unroll
            for (int c = 0; c < 4; c++)
                xv[r * 4 + c] = __ldg(ip + r * WIN + c);

        // row stage: t = B^T d  (combine rows)
        float tr[16];
        #pragma unroll
        for (int c = 0; c < 4; c++) {
            tr[0  + c] = xv[0 + c] - xv[8 + c];
            tr[4  + c] = xv[4 + c] + xv[8 + c];
            tr[8  + c] = xv[8 + c] - xv[4 + c];
            tr[12 + c] = xv[4 + c] - xv[12 + c];
        }
        // col stage: V = t B  (combine cols)
        float v[16];
        #pragma unroll
        for (int r = 0; r < 4; r++) {
            float a0 = tr[r * 4], a1 = tr[r * 4 + 1], a2 = tr[r * 4 + 2], a3 = tr[r * 4 + 3];
            v[r * 4 + 0] = a0 - a2;
            v[r * 4 + 1] = a1 + a2;
            v[r * 4 + 2] = a2 - a1;
            v[r * 4 + 3] = a1 - a3;
        }

        const ulonglong2* wc = wbase + (size_t)ci * 32;
        #pragma unroll
        for (int j = 0; j < 16; j++) {
            u64 vp = pack2(v[j], v[j]);
            ulonglong2 wA = __ldg(wc + 2 * j);       // co pairs {0,1},{2,3}
            ulonglong2 wB = __ldg(wc + 2 * j + 1);   // co pairs {4,5},{6,7}
            acc[0][j] = fma2(vp, wA.x, acc[0][j]);
            acc[1][j] = fma2(vp, wA.y, acc[1][j]);
            acc[2][j] = fma2(vp, wB.x, acc[2][j]);
            acc[3][j] = fma2(vp, wB.y, acc[3][j]);
        }
    }

    // epilogue: Y = A^T M A per channel, pooled max + bias + relu
    #pragma unroll
    for (int p = 0; p < 4; p++) {
        float ml[16], mh[16];
        #pragma unroll
        for (int j = 0; j < 16; j++) unpack2(acc[p][j], ml[j], mh[j]);

        float res[2];
        #pragma unroll
        for (int l = 0; l < 2; l++) {
            const float* m = l ? mh : ml;
            float s00 = m[0] + m[4] + m[8],  s01 = m[1] + m[5] + m[9];
            float s02 = m[2] + m[6] + m[10], s03 = m[3] + m[7] + m[11];
            float s10 = m[4] - m[8] - m[12], s11 = m[5] - m[9] - m[13];
            float s12 = m[6] - m[10] - m[14], s13 = m[7] - m[11] - m[15];
            float y00 = s00 + s01 + s02;
            float y01 = s01 - s02 - s03;
            float y10 = s10 + s11 + s12;
            float y11 = s11 - s12 - s13;
            res[l] = fmaxf(fmaxf(y00, y01), fmaxf(y10, y11));
        }
        float mlo = res[0] + __ldg(bias + co0 + 2 * p);
        float mhi = res[1] + __ldg(bias + co0 + 2 * p + 1);
        size_t o0 = (((size_t)b * COUT + co0 + 2 * p) * HP + ph) * WP + pw;
        out[o0]                   = fmaxf(mlo, 0.0f);
        out[o0 + (size_t)HP * WP] = fmaxf(mhi, 0.0f);
    }
}

// ---------------- split-K partial GEMM (FFMA2) ----------------
__global__ __launch_bounds__(256)
void gemm64_part(const float* __restrict__ A, const float* __restrict__ B,
                 float* __restrict__ Cpart, int M, int N, int K, int Ks)
{
    const int BM = 64, BN = 64, BK = 16;
    __shared__ float As[BK][BM + 1];
    __shared__ float Bs[BK][BN];
    int tx = threadIdx.x % 16, ty = threadIdx.x / 16;
    int m0 = blockIdx.y * BM, n0 = blockIdx.x * BN;
    int z = blockIdx.z;
    int k0 = z * Ks;
    float* Cz = Cpart + (size_t)z * M * N;

    u64 acc[4][2] = {};
    for (int kk = k0; kk < k0 + Ks; kk += BK) {
        #pragma unroll
        for (int i = 0; i < 4; i++) {
            int l = threadIdx.x + i * 256;
            int m = l / 16, k = l % 16;
            As[k][m] = A[(size_t)(m0 + m) * K + kk + k];
        }
        #pragma unroll
        for (int i = 0; i < 4; i++) {
            int l = threadIdx.x + i * 256;
            int n = l % 64, k = l / 64;
            Bs[k][n] = B[(size_t)(kk + k) * N + n0 + n];
        }
        __syncthreads();
        #pragma unroll
        for (int k = 0; k < BK; k++) {
            u64 b0 = *reinterpret_cast<const u64*>(&Bs[k][tx * 4]);
            u64 b1 = *reinterpret_cast<const u64*>(&Bs[k][tx * 4 + 2]);
            #pragma unroll
            for (int i = 0; i < 4; i++) {
                float a = As[k][ty * 4 + i];
                u64 ap = pack2(a, a);
                acc[i][0] = fma2(ap, b0, acc[i][0]);
                acc[i][1] = fma2(ap, b1, acc[i][1]);
            }
        }
        __syncthreads();
    }

    #pragma unroll
    for (int i = 0; i < 4; i++) {
        int m = m0 + ty * 4 + i;
        #pragma unroll
        for (int j = 0; j < 2; j++) {
            float lo, hi;
            unpack2(acc[i][j], lo, hi);
            int n = n0 + tx * 4 + j * 2;
            Cz[(size_t)m * N + n]     = lo;
            Cz[(size_t)m * N + n + 1] = hi;
        }
    }
}

__global__ void combine_tanh(const float* __restrict__ part, const float* __restrict__ bias,
                             float* __restrict__ C, int M, int N)
{
    int i = blockIdx.x * blockDim.x + threadIdx.x;
    if (i >= M * N) return;
    int n = i % N;
    C[i] = tanhf(part[i] + part[(size_t)M * N + i] + __ldg(bias + n));
}

// ---------------- small FC (fc3: 2048 -> 62) ----------------
__global__ void fc_small(const float* __restrict__ A, const float* __restrict__ W,
                         const float* __restrict__ bias, float* __restrict__ C,
                         int N, int K)
{
    int n = threadIdx.x;
    int m = blockIdx.x;
    if (n >= N) return;
    float acc = __ldg(bias + n);
    const float* a = A + (size_t)m * K;
    #pragma unroll 4
    for (int k = 0; k < K; k++)
        acc = fmaf(__ldg(a + k), __ldg(W + (size_t)k * N + n), acc);
    C[(size_t)m * N + n] = acc;
}

// ---------------- trajectory assembly ----------------
__global__ void traj_kernel(const float* __restrict__ p, const float* __restrict__ dict,
                            float* __restrict__ out)
{
    int b = blockIdx.x;
    __shared__ float sx[SSEG], sy[SSEG], s1[SSEG], s2[SSEG];
    __shared__ int sidx[SSEG];

    if (threadIdx.x == 0) {
        float cx = p[b * OUTDIM + 0];
        float cy = p[b * OUTDIM + 1];
        for (int s = 0; s < SSEG; s++) {
            float f0  = p[b * OUTDIM + 2 + s * 3 + 0];
            float sc1 = p[b * OUTDIM + 2 + s * 3 + 1];
            float sc2 = p[b * OUTDIM + 2 + s * 3 + 2];
            float r = rintf(f0);
            r = fminf(fmaxf(r, 0.0f), (float)(DDICT - 1));
            int id = (int)r;
            sidx[s] = id; s1[s] = sc1; s2[s] = sc2;
            sx[s] = cx; sy[s] = cy;
            cx += dict[((size_t)id * LSEG + (LSEG - 1)) * 2 + 0] * sc1;
            cy += dict[((size_t)id * LSEG + (LSEG - 1)) * 2 + 1] * sc2;
        }
    }
    __syncthreads();

    for (int i = threadIdx.x; i < SSEG * LSEG; i += blockDim.x) {
        int s = i / LSEG, l = i % LSEG;
        int id = sidx[s];
        float bx = dict[((size_t)id * LSEG + l) * 2 + 0];
        float by = dict[((size_t)id * LSEG + l) * 2 + 1];
        out[((size_t)b * SSEG * LSEG + i) * 2 + 0] = fmaf(bx, s1[s], sx[s]);
        out[((size_t)b * SSEG * LSEG + i) * 2 + 1] = fmaf(by, s2[s], sy[s]);
    }
}

// ---------------- launch ----------------
extern "C" void kernel_launch(void* const* d_in, const int* in_sizes, int n_in,
                              void* d_out, int out_size)
{
    const float* x   = (const float*)d_in[0];
    const float* w1  = (const float*)d_in[1];
    const float* b1  = (const float*)d_in[2];
    const float* w2  = (const float*)d_in[3];
    const float* b2  = (const float*)d_in[4];
    const float* w3  = (const float*)d_in[5];
    const float* b3  = (const float*)d_in[6];
    const float* w4  = (const float*)d_in[7];
    const float* b4  = (const float*)d_in[8];
    const float* fw1 = (const float*)d_in[9];
    const float* fb1 = (const float*)d_in[10];
    const float* fw2 = (const float*)d_in[11];
    const float* fb2 = (const float*)d_in[12];
    const float* fw3 = (const float*)d_in[13];
    const float* fb3 = (const float*)d_in[14];
    const float* dict= (const float*)d_in[15];
    float* out = (float*)d_out;

    float *h1, *h2, *h3, *h4, *a1, *a2, *pp, *part;
    float *w1u, *w2u, *w3u, *w4u;
    cudaGetSymbolAddress((void**)&h1,  g_h1);
    cudaGetSymbolAddress((void**)&h2,  g_h2);
    cudaGetSymbolAddress((void**)&h3,  g_h3);
    cudaGetSymbolAddress((void**)&h4,  g_h4);
    cudaGetSymbolAddress((void**)&a1,  g_a1);
    cudaGetSymbolAddress((void**)&a2,  g_a2);
    cudaGetSymbolAddress((void**)&pp,  g_p);
    cudaGetSymbolAddress((void**)&part,g_part);
    cudaGetSymbolAddress((void**)&w1u, g_w1u);
    cudaGetSymbolAddress((void**)&w2u, g_w2u);
    cudaGetSymbolAddress((void**)&w3u, g_w3u);
    cudaGetSymbolAddress((void**)&w4u, g_w4u);

    // Winograd weight transforms
    repack_wino<<<(64*3     + 255) / 256, 256>>>(w1, w1u, 3,   64);
    repack_wino<<<(128*64   + 255) / 256, 256>>>(w2, w2u, 64,  128);
    repack_wino<<<(256*128  + 255) / 256, 256>>>(w3, w3u, 128, 256);
    repack_wino<<<(512*256  + 255) / 256, 256>>>(w4, w4u, 256, 512);

    // stage 1: (128,3,100,100) -> (128,64,49,49)
    {
        int total = NB * (64/8) * 49 * 49;
        conv_wino<3,100,100,49,49,64><<<(total + 255) / 256, 256>>>(x, w1u, b1, h1);
    }
    // stage 2: -> (128,128,23,23)
    {
        int total = NB * (128/8) * 23 * 23;
        conv_wino<64,49,49,23,23,128><<<(total + 255) / 256, 256>>>(h1, w2u, b2, h2);
    }
    // stage 3: -> (128,256,10,10)
    {
        int total = NB * (256/8) * 10 * 10;
        conv_wino<128,23,23,10,10,256><<<(total + 255) / 256, 256>>>(h2, w3u, b3, h3);
    }
    // stage 4: -> (128,512,4,4) == flatten (128, 8192)
    {
        int total = NB * (512/8) * 4 * 4;
        conv_wino<256,10,10,4,4,512><<<(total + 255) / 256, 256>>>(h3, w4u, b4, h4);
    }

    // fc1: (128,8192) @ (8192,2048) + tanh, split-K=2
    {
        dim3 grid(2048 / 64, NB / 64, 2);
        gemm64_part<<<grid, 256>>>(h4, fw1, part, NB, 2048, 8192, 4096);
        combine_tanh<<<(NB * 2048 + 255) / 256, 256>>>(part, fb1, a1, NB, 2048);
    }
    // fc2: (128,2048) @ (2048,2048) + tanh, split-K=2
    {
        dim3 grid(2048 / 64, NB / 64, 2);
        gemm64_part<<<grid, 256>>>(a1, fw2, part, NB, 2048, 2048, 1024);
        combine_tanh<<<(NB * 2048 + 255) / 256, 256>>>(part, fb2, a2, NB, 2048);
    }
    // fc3: (128,2048) @ (2048,62)
    fc_small<<<NB, 64>>>(a2, fw3, fb3, pp, OUTDIM, 2048);

    // trajectory assembly -> (128, 4000, 2)
    traj_kernel<<<NB, 256>>>(pp, dict, out);
}

// round 9
// speedup vs baseline: 2.7924x; 2.7924x over previous
#include <cuda_runtime.h>
#include <cuda_fp16.h>
#include <math.h>
#include <stdint.h>

typedef unsigned long long u64;

// ---------------- problem constants ----------------
#define NB   128
#define SSEG 20
#define DDICT 1000
#define LSEG 200
#define OUTDIM 62      // 2 + 3*20

// ---------------- f32x2 helpers ----------------
__device__ __forceinline__ u64 pack2(float a, float b) {
    u64 r; asm("mov.b64 %0, {%1, %2};" : "=l"(r) : "f"(a), "f"(b)); return r;
}
__device__ __forceinline__ u64 fma2(u64 a, u64 b, u64 c) {
    u64 d; asm("fma.rn.f32x2 %0, %1, %2, %3;" : "=l"(d) : "l"(a), "l"(b), "l"(c)); return d;
}
__device__ __forceinline__ void unpack2(u64 v, float& lo, float& hi) {
    asm("mov.b64 {%0, %1}, %2;" : "=f"(lo), "=f"(hi) : "l"(v));
}

// ---------------- fp16 mma helper: D += A(16x16) * B(16x8), f32 accum ----------------
__device__ __forceinline__ void mma16816(float* d, const uint32_t* a, const uint32_t* b) {
    asm volatile(
        "mma.sync.aligned.m16n8k16.row.col.f32.f16.f16.f32 "
        "{%0,%1,%2,%3}, {%4,%5,%6,%7}, {%8,%9}, {%0,%1,%2,%3};"
        : "+f"(d[0]), "+f"(d[1]), "+f"(d[2]), "+f"(d[3])
        : "r"(a[0]), "r"(a[1]), "r"(a[2]), "r"(a[3]), "r"(b[0]), "r"(b[1]));
}

// ---------------- scratch (device globals; conv inputs padded for shifted reads) --------
__device__ float g_h1[(size_t)NB*64*49*49 + 8192];
__device__ float g_h2[(size_t)NB*128*23*23 + 8192];
__device__ float g_h3[(size_t)NB*256*10*10 + 8192];
__device__ float g_h4[(size_t)NB*512*4*4];
__device__ float g_a1[NB*2048];
__device__ float g_a2[NB*2048];
__device__ float g_part[2*NB*2048];
__device__ float g_p [NB*OUTDIM];
__device__ float g_w1k[64*3*9];
// fp16-split weights: [kh][co][kw*CIN+ci], hi & lo halves
__device__ __align__(16) __half g_w2h[9*128*64],  g_w2l[9*128*64];
__device__ __align__(16) __half g_w3h[9*256*128], g_w3l[9*256*128];
__device__ __align__(16) __half g_w4h[9*512*256], g_w4l[9*512*256];

// ---------------- weight repack for scalar conv1 ----------------
__global__ void repack_wk(const float* __restrict__ w, float* __restrict__ wk, int CIN, int COUT)
{
    int i = blockIdx.x * blockDim.x + threadIdx.x;
    int total = COUT * CIN * 9;
    if (i >= total) return;
    int c  = i % 8;
    int k  = (i / 8) % 9;
    int ci = (i / 72) % CIN;
    int cg = i / (72 * CIN);
    wk[i] = w[((size_t)(cg * 8 + c) * CIN + ci) * 9 + k];
}

// ---------------- weight repack + fp16 split: -> [kh][co][kw*CIN+ci] ----------------
__global__ void repack_h2(const float* __restrict__ w, __half* __restrict__ whi,
                          __half* __restrict__ wlo, int CIN, int COUT)
{
    int i = blockIdx.x * blockDim.x + threadIdx.x;
    int tot = COUT * CIN * 9;
    if (i >= tot) return;
    int kw = i % 3, kh = (i / 3) % 3, ci = (i / 9) % CIN, co = i / (9 * CIN);
    float v = w[i];
    __half hi = __float2half_rn(v);
    __half lo = __float2half_rn(v - __half2float(hi));
    size_t d = (((size_t)kh * COUT + co) * 3 + kw) * CIN + ci;
    whi[d] = hi;
    wlo[d] = lo;
}

// ---------------- fp16-split mma.sync fused conv3x3 + bias + maxpool2 + relu ------------
// One CTA: one image, ROWS conv rows (128 pixel lanes), 128-wide COUT tile.
// 9 shifted GEMMs over ci chunks of 32, fp16 hi/lo 3-term split, f32 accum.
// Warp w: co block (w>>1)*32 (2x m16), pixel block (w&1)*64 (8x n8).
// SMEM tiles [row][k] half-major, stride 40 halves (80B): frag LDS conflict-free.
template<int CIN, int H, int W, int COUT, int ROWS>
__global__ __launch_bounds__(256, 2)
void conv_mma(const float* __restrict__ src, const __half* __restrict__ whi,
              const __half* __restrict__ wlo, const float* __restrict__ bias,
              float* __restrict__ dst)
{
    constexpr int HW  = H * W;
    constexpr int KCH = CIN / 32;
    constexpr int NCH = 9 * KCH;
    constexpr int PR  = ROWS / 2;
    constexpr int PWW = (W - 2) / 2;
    constexpr int PHH = (H - 2) / 2;
    constexpr int ST2 = 40;             // halves per smem tile row (32 k + 8 pad)
    constexpr int TILE = 128 * ST2;     // halves per tile
    constexpr int EST = 132;            // epilogue row stride (floats)

    extern __shared__ __align__(16) char smraw[];
    __half* Ah = (__half*)smraw;                 // [128][ST2]
    __half* Al = Ah + TILE;
    __half* Bh = Ah + 2 * TILE;
    __half* Bl = Ah + 3 * TILE;
    float*  eps = (float*)smraw;                 // epilogue overlay [128][EST]

    const int tid  = threadIdx.x;
    const int wid  = tid >> 5;
    const int lane = tid & 31;
    const int l4   = lane >> 2;
    const int lm   = lane & 3;

    const int img = blockIdx.y;
    const int r0  = blockIdx.x * ROWS;
    const int m0  = blockIdx.z * 128;
    const float* ib = src + (size_t)img * CIN * HW + r0 * W;

    const int co   = tid & 127;         // A fill row
    const int half = tid >> 7;          // k half (16 k each)
    const int bn   = tid & 127;         // B fill row (pixel)

    const int co0w = (wid >> 1) * 32;
    const int n0w  = (wid & 1) * 64;

    float acc[2][8][4];
    #pragma unroll
    for (int mb = 0; mb < 2; mb++)
        #pragma unroll
        for (int nb = 0; nb < 8; nb++)
            #pragma unroll
            for (int j = 0; j < 4; j++) acc[mb][nb][j] = 0.0f;

    for (int s = 0; s < NCH; s++) {
        int cc  = s % KCH;
        int kwv = (s / KCH) % 3;
        int khv = s / (3 * KCH);
        int ci0 = cc * 32;

        if (s > 0) __syncthreads();

        // ---- A tile [co128][k32] halves: weights hi+lo, 16 halves = 2x uint4 each ----
        {
            size_t off = (((size_t)khv * COUT + m0 + co) * 3 + kwv) * CIN + ci0 + half * 16;
            uint4 vh0 = *(const uint4*)(whi + off);       // halves 0-7
            uint4 vh1 = *(const uint4*)(whi + off + 8);   // halves 8-15
            uint4 vl0 = *(const uint4*)(wlo + off);
            uint4 vl1 = *(const uint4*)(wlo + off + 8);
            uint32_t sa = co * ST2 + half * 16;  // half index
            *(uint4*)(Ah + sa)     = vh0;
            *(uint4*)(Ah + sa + 8) = vh1;
            *(uint4*)(Al + sa)     = vl0;
            *(uint4*)(Al + sa + 8) = vl1;
        }
        // ---- B tile [n128][k32] halves: shifted strided reads, fp16 split ----
        {
            const float* bp = ib + bn + khv * W + kwv;
            #pragma unroll
            for (int i = 0; i < 8; i++) {
                int k = half * 16 + 2 * i;
                float x0 = __ldg(bp + (size_t)(ci0 + k) * HW);
                float x1 = __ldg(bp + (size_t)(ci0 + k + 1) * HW);
                __half h0 = __float2half_rn(x0);
                __half h1 = __float2half_rn(x1);
                __half l0 = __float2half_rn(x0 - __half2float(h0));
                __half l1 = __float2half_rn(x1 - __half2float(h1));
                uint32_t sa = bn * ST2 + k;
                *(__half2*)(Bh + sa) = __halves2half2(h0, h1);
                *(__half2*)(Bl + sa) = __halves2half2(l0, l1);
            }
        }
        __syncthreads();

        const uint32_t* Ah32 = (const uint32_t*)Ah;
        const uint32_t* Al32 = (const uint32_t*)Al;
        const uint32_t* Bh32 = (const uint32_t*)Bh;
        const uint32_t* Bl32 = (const uint32_t*)Bl;
        constexpr int SU = ST2 / 2;     // u32 (half2) per row = 20

        #pragma unroll
        for (int ks = 0; ks < 2; ks++) {
            int k0 = ks * 8;            // in half2 units
            uint32_t ah[2][4], al[2][4];
            #pragma unroll
            for (int mb = 0; mb < 2; mb++) {
                int m = co0w + mb * 16 + l4;
                ah[mb][0] = Ah32[m * SU + k0 + lm];
                ah[mb][1] = Ah32[(m + 8) * SU + k0 + lm];
                ah[mb][2] = Ah32[m * SU + k0 + lm + 4];
                ah[mb][3] = Ah32[(m + 8) * SU + k0 + lm + 4];
                al[mb][0] = Al32[m * SU + k0 + lm];
                al[mb][1] = Al32[(m + 8) * SU + k0 + lm];
                al[mb][2] = Al32[m * SU + k0 + lm + 4];
                al[mb][3] = Al32[(m + 8) * SU + k0 + lm + 4];
            }
            #pragma unroll
            for (int nb = 0; nb < 8; nb++) {
                int n = n0w + nb * 8 + l4;
                uint32_t bh[2], bl[2];
                bh[0] = Bh32[n * SU + k0 + lm];
                bh[1] = Bh32[n * SU + k0 + lm + 4];
                bl[0] = Bl32[n * SU + k0 + lm];
                bl[1] = Bl32[n * SU + k0 + lm + 4];
                #pragma unroll
                for (int mb = 0; mb < 2; mb++) {
                    mma16816(acc[mb][nb], ah[mb], bh);
                    mma16816(acc[mb][nb], ah[mb], bl);
                    mma16816(acc[mb][nb], al[mb], bh);
                }
            }
        }
    }

    __syncthreads();   // done with tiles; reuse smem for epilogue

    // ---- write accumulators to eps[co][pix] ----
    #pragma unroll
    for (int mb = 0; mb < 2; mb++) {
        #pragma unroll
        for (int nb = 0; nb < 8; nb++) {
            int n = n0w + nb * 8 + 2 * lm;
            int c_lo = co0w + mb * 16 + l4;
            *(float2*)&eps[c_lo * EST + n]       = make_float2(acc[mb][nb][0], acc[mb][nb][1]);
            *(float2*)&eps[(c_lo + 8) * EST + n] = make_float2(acc[mb][nb][2], acc[mb][nb][3]);
        }
    }
    __syncthreads();

    // ---- pool + bias + relu ----
    for (int t = tid; t < 128 * PR * PWW; t += 256) {
        int pw = t % PWW;
        int r  = t / PWW;
        int pr = r % PR;
        int c  = r / PR;
        int c0 = (2 * pr) * W + 2 * pw;
        const float* e = eps + c * EST;
        float v = fmaxf(fmaxf(e[c0], e[c0 + 1]), fmaxf(e[c0 + W], e[c0 + W + 1]))
                  + __ldg(bias + m0 + c);
        dst[(((size_t)img * COUT + m0 + c) * PHH + (r0 >> 1) + pr) * PWW + pw] = fmaxf(v, 0.0f);
    }
}

// ---------------- scalar conv stage 1 (CIN=3) — FFMA2 path ----------------
template<int CIN, int HIN, int WIN, int HP, int WP, int COUT>
__global__ __launch_bounds__(256)
void conv_pool_relu2(const float* __restrict__ in,
                     const float* __restrict__ wk,
                     const float* __restrict__ bias,
                     float* __restrict__ out)
{
    constexpr int COG = COUT / 8;
    int idx = blockIdx.x * blockDim.x + threadIdx.x;
    const int total = NB * COG * HP * WP;
    if (idx >= total) return;

    int pw = idx % WP;  int t = idx / WP;
    int ph = t % HP;    t /= HP;
    int cg = t % COG;   t /= COG;
    int b  = t;
    int co0 = cg * 8;

    u64 acc2[4][4];
    #pragma unroll
    for (int p = 0; p < 4; p++)
        #pragma unroll
        for (int j = 0; j < 4; j++) acc2[p][j] = 0ull;

    const float* inb = in + ((size_t)b * CIN * HIN + 2 * ph) * WIN + 2 * pw;
    const ulonglong2* __restrict__ wbase =
        reinterpret_cast<const ulonglong2*>(wk + (size_t)cg * CIN * 72);

    for (int ci = 0; ci < CIN; ci++) {
        const float* ip = inb + (size_t)ci * HIN * WIN;
        u64 xx[16];
        #pragma unroll
        for (int r = 0; r < 4; r++)
            #pragma unroll
            for (int c = 0; c < 4; c++) {
                float v = __ldg(ip + r * WIN + c);
                xx[r * 4 + c] = pack2(v, v);
            }
        const ulonglong2* wp = wbase + (size_t)ci * 18;
        #pragma unroll
        for (int k = 0; k < 9; k++) {
            ulonglong2 wA = wp[2 * k];
            ulonglong2 wB = wp[2 * k + 1];
            u64 wpair[4] = {wA.x, wA.y, wB.x, wB.y};
            int kh = k / 3, kw = k % 3;
            #pragma unroll
            for (int p = 0; p < 4; p++)
                #pragma unroll
                for (int dy = 0; dy < 2; dy++)
                    #pragma unroll
                    for (int dx = 0; dx < 2; dx++)
                        acc2[p][dy * 2 + dx] =
                            fma2(xx[(dy + kh) * 4 + dx + kw], wpair[p], acc2[p][dy * 2 + dx]);
        }
    }

    #pragma unroll
    for (int p = 0; p < 4; p++) {
        float l0, h0, l1, h1, l2, h2, l3, h3;
        unpack2(acc2[p][0], l0, h0);
        unpack2(acc2[p][1], l1, h1);
        unpack2(acc2[p][2], l2, h2);
        unpack2(acc2[p][3], l3, h3);
        float mlo = fmaxf(fmaxf(l0, l1), fmaxf(l2, l3)) + __ldg(bias + co0 + 2 * p);
        float mhi = fmaxf(fmaxf(h0, h1), fmaxf(h2, h3)) + __ldg(bias + co0 + 2 * p + 1);
        size_t o0 = (((size_t)b * COUT + co0 + 2 * p) * HP + ph) * WP + pw;
        out[o0]                   = fmaxf(mlo, 0.0f);
        out[o0 + (size_t)HP * WP] = fmaxf(mhi, 0.0f);
    }
}

// ---------------- FFMA2 tiled SGEMM ----------------
template<int ACT>
__global__ __launch_bounds__(256)
void gemm64v2(const float* __restrict__ A, const float* __restrict__ B,
              const float* __restrict__ bias, float* __restrict__ C,
              int M, int N, int K)
{
    const int BM = 64, BN = 64, BK = 16;
    __shared__ float As[BK][BM + 1];
    __shared__ float Bs[BK][BN];
    int tx = threadIdx.x % 16, ty = threadIdx.x / 16;
    int m0 = blockIdx.y * BM, n0 = blockIdx.x * BN;

    u64 acc[4][2] = {};
    for (int kk = 0; kk < K; kk += BK) {
        #pragma unroll
        for (int i = 0; i < 4; i++) {
            int l = threadIdx.x + i * 256;
            int m = l / 16, k = l % 16;
            As[k][m] = A[(size_t)(m0 + m) * K + kk + k];
        }
        #pragma unroll
        for (int i = 0; i < 4; i++) {
            int l = threadIdx.x + i * 256;
            int n = l % 64, k = l / 64;
            Bs[k][n] = B[(size_t)(kk + k) * N + n0 + n];
        }
        __syncthreads();
        #pragma unroll
        for (int k = 0; k < BK; k++) {
            u64 b0 = *reinterpret_cast<const u64*>(&Bs[k][tx * 4]);
            u64 b1 = *reinterpret_cast<const u64*>(&Bs[k][tx * 4 + 2]);
            #pragma unroll
            for (int i = 0; i < 4; i++) {
                float a = As[k][ty * 4 + i];
                u64 ap = pack2(a, a);
                acc[i][0] = fma2(ap, b0, acc[i][0]);
                acc[i][1] = fma2(ap, b1, acc[i][1]);
            }
        }
        __syncthreads();
    }

    #pragma unroll
    for (int i = 0; i < 4; i++) {
        int m = m0 + ty * 4 + i;
        #pragma unroll
        for (int j = 0; j < 2; j++) {
            float lo, hi;
            unpack2(acc[i][j], lo, hi);
            int n = n0 + tx * 4 + j * 2;
            float v0 = lo + __ldg(bias + n);
            float v1 = hi + __ldg(bias + n + 1);
            if (ACT == 1) { v0 = tanhf(v0); v1 = tanhf(v1); }
            C[(size_t)m * N + n]     = v0;
            C[(size_t)m * N + n + 1] = v1;
        }
    }
}

// ---------------- split-K partial GEMM ----------------
__global__ __launch_bounds__(256)
void gemm64_part(const float* __restrict__ A, const float* __restrict__ B,
                 float* __restrict__ Cpart, int M, int N, int K, int Ks)
{
    const int BM = 64, BN = 64, BK = 16;
    __shared__ float As[BK][BM + 1];
    __shared__ float Bs[BK][BN];
    int tx = threadIdx.x % 16, ty = threadIdx.x / 16;
    int m0 = blockIdx.y * BM, n0 = blockIdx.x * BN;
    int z = blockIdx.z;
    int k0 = z * Ks;
    float* Cz = Cpart + (size_t)z * M * N;

    u64 acc[4][2] = {};
    for (int kk = k0; kk < k0 + Ks; kk += BK) {
        #pragma unroll
        for (int i = 0; i < 4; i++) {
            int l = threadIdx.x + i * 256;
            int m = l / 16, k = l % 16;
            As[k][m] = A[(size_t)(m0 + m) * K + kk + k];
        }
        #pragma unroll
        for (int i = 0; i < 4; i++) {
            int l = threadIdx.x + i * 256;
            int n = l % 64, k = l / 64;
            Bs[k][n] = B[(size_t)(kk + k) * N + n0 + n];
        }
        __syncthreads();
        #pragma unroll
        for (int k = 0; k < BK; k++) {
            u64 b0 = *reinterpret_cast<const u64*>(&Bs[k][tx * 4]);
            u64 b1 = *reinterpret_cast<const u64*>(&Bs[k][tx * 4 + 2]);
            #pragma unroll
            for (int i = 0; i < 4; i++) {
                float a = As[k][ty * 4 + i];
                u64 ap = pack2(a, a);
                acc[i][0] = fma2(ap, b0, acc[i][0]);
                acc[i][1] = fma2(ap, b1, acc[i][1]);
            }
        }
        __syncthreads();
    }

    #pragma unroll
    for (int i = 0; i < 4; i++) {
        int m = m0 + ty * 4 + i;
        #pragma unroll
        for (int j = 0; j < 2; j++) {
            float lo, hi;
            unpack2(acc[i][j], lo, hi);
            int n = n0 + tx * 4 + j * 2;
            Cz[(size_t)m * N + n]     = lo;
            Cz[(size_t)m * N + n + 1] = hi;
        }
    }
}

__global__ void combine_tanh(const float* __restrict__ part, const float* __restrict__ bias,
                             float* __restrict__ C, int M, int N)
{
    int i = blockIdx.x * blockDim.x + threadIdx.x;
    if (i >= M * N) return;
    int n = i % N;
    C[i] = tanhf(part[i] + part[(size_t)M * N + i] + __ldg(bias + n));
}

// ---------------- small FC (fc3: 2048 -> 62) ----------------
__global__ void fc_small(const float* __restrict__ A, const float* __restrict__ W,
                         const float* __restrict__ bias, float* __restrict__ C,
                         int N, int K)
{
    int n = threadIdx.x;
    int m = blockIdx.x;
    if (n >= N) return;
    float acc = __ldg(bias + n);
    const float* a = A + (size_t)m * K;
    #pragma unroll 4
    for (int k = 0; k < K; k++)
        acc = fmaf(__ldg(a + k), __ldg(W + (size_t)k * N + n), acc);
    C[(size_t)m * N + n] = acc;
}

// ---------------- trajectory assembly ----------------
__global__ void traj_kernel(const float* __restrict__ p, const float* __restrict__ dict,
                            float* __restrict__ out)
{
    int b = blockIdx.x;
    __shared__ float sx[SSEG], sy[SSEG], s1[SSEG], s2[SSEG];
    __shared__ int sidx[SSEG];

    if (threadIdx.x == 0) {
        float cx = p[b * OUTDIM + 0];
        float cy = p[b * OUTDIM + 1];
        for (int s = 0; s < SSEG; s++) {
            float f0  = p[b * OUTDIM + 2 + s * 3 + 0];
            float sc1 = p[b * OUTDIM + 2 + s * 3 + 1];
            float sc2 = p[b * OUTDIM + 2 + s * 3 + 2];
            float r = rintf(f0);
            r = fminf(fmaxf(r, 0.0f), (float)(DDICT - 1));
            int id = (int)r;
            sidx[s] = id; s1[s] = sc1; s2[s] = sc2;
            sx[s] = cx; sy[s] = cy;
            cx += dict[((size_t)id * LSEG + (LSEG - 1)) * 2 + 0] * sc1;
            cy += dict[((size_t)id * LSEG + (LSEG - 1)) * 2 + 1] * sc2;
        }
    }
    __syncthreads();

    for (int i = threadIdx.x; i < SSEG * LSEG; i += blockDim.x) {
        int s = i / LSEG, l = i % LSEG;
        int id = sidx[s];
        float bx = dict[((size_t)id * LSEG + l) * 2 + 0];
        float by = dict[((size_t)id * LSEG + l) * 2 + 1];
        out[((size_t)b * SSEG * LSEG + i) * 2 + 0] = fmaf(bx, s1[s], sx[s]);
        out[((size_t)b * SSEG * LSEG + i) * 2 + 1] = fmaf(by, s2[s], sy[s]);
    }
}

// ---------------- launch ----------------
extern "C" void kernel_launch(void* const* d_in, const int* in_sizes, int n_in,
                              void* d_out, int out_size)
{
    const float* x   = (const float*)d_in[0];
    const float* w1  = (const float*)d_in[1];
    const float* b1  = (const float*)d_in[2];
    const float* w2  = (const float*)d_in[3];
    const float* b2  = (const float*)d_in[4];
    const float* w3  = (const float*)d_in[5];
    const float* b3  = (const float*)d_in[6];
    const float* w4  = (const float*)d_in[7];
    const float* b4  = (const float*)d_in[8];
    const float* fw1 = (const float*)d_in[9];
    const float* fb1 = (const float*)d_in[10];
    const float* fw2 = (const float*)d_in[11];
    const float* fb2 = (const float*)d_in[12];
    const float* fw3 = (const float*)d_in[13];
    const float* fb3 = (const float*)d_in[14];
    const float* dict= (const float*)d_in[15];
    float* out = (float*)d_out;

    float *h1, *h2, *h3, *h4, *a1, *a2, *pp, *part, *w1k;
    __half *w2h, *w2l, *w3h, *w3l, *w4h, *w4l;
    cudaGetSymbolAddress((void**)&h1,  g_h1);
    cudaGetSymbolAddress((void**)&h2,  g_h2);
    cudaGetSymbolAddress((void**)&h3,  g_h3);
    cudaGetSymbolAddress((void**)&h4,  g_h4);
    cudaGetSymbolAddress((void**)&a1,  g_a1);
    cudaGetSymbolAddress((void**)&a2,  g_a2);
    cudaGetSymbolAddress((void**)&pp,  g_p);
    cudaGetSymbolAddress((void**)&part,g_part);
    cudaGetSymbolAddress((void**)&w1k, g_w1k);
    cudaGetSymbolAddress((void**)&w2h, g_w2h);
    cudaGetSymbolAddress((void**)&w2l, g_w2l);
    cudaGetSymbolAddress((void**)&w3h, g_w3h);
    cudaGetSymbolAddress((void**)&w3l, g_w3l);
    cudaGetSymbolAddress((void**)&w4h, g_w4h);
    cudaGetSymbolAddress((void**)&w4l, g_w4l);

    // dyn smem: max(4 half-tiles 40960 B, epilogue 128*132*4 = 67584 B)
    const int SMEM_DYN = 128 * 132 * 4;   // 67584
    cudaFuncSetAttribute((const void*)conv_mma<64,49,49,128,2>,
                         cudaFuncAttributeMaxDynamicSharedMemorySize, SMEM_DYN);
    cudaFuncSetAttribute((const void*)conv_mma<128,23,23,256,4>,
                         cudaFuncAttributeMaxDynamicSharedMemorySize, SMEM_DYN);
    cudaFuncSetAttribute((const void*)conv_mma<256,10,10,512,8>,
                         cudaFuncAttributeMaxDynamicSharedMemorySize, SMEM_DYN);

    // weight repacks
    repack_wk<<<(64*3*9 + 255) / 256, 256>>>(w1, w1k, 3, 64);
    repack_h2<<<(128*64*9  + 255) / 256, 256>>>(w2, w2h, w2l, 64,  128);
    repack_h2<<<(256*128*9 + 255) / 256, 256>>>(w3, w3h, w3l, 128, 256);
    repack_h2<<<(512*256*9 + 255) / 256, 256>>>(w4, w4h, w4l, 256, 512);

    // stage 1 (scalar FFMA2): (128,3,100,100) -> (128,64,49,49)
    {
        int total = NB * (64/8) * 49 * 49;
        conv_pool_relu2<3,100,100,49,49,64><<<(total + 255) / 256, 256>>>(x, w1k, b1, h1);
    }
    // stage 2 (fp16-split mma): -> (128,128,23,23)
    conv_mma<64,49,49,128,2><<<dim3(23, NB, 1), 256, SMEM_DYN>>>(h1, w2h, w2l, b2, h2);
    // stage 3: -> (128,256,10,10)
    conv_mma<128,23,23,256,4><<<dim3(5, NB, 2), 256, SMEM_DYN>>>(h2, w3h, w3l, b3, h3);
    // stage 4: -> (128,512,4,4)
    conv_mma<256,10,10,512,8><<<dim3(1, NB, 4), 256, SMEM_DYN>>>(h3, w4h, w4l, b4, h4);

    // fc1: (128,8192) @ (8192,2048) + tanh, split-K=2
    {
        dim3 grid(2048 / 64, NB / 64, 2);
        gemm64_part<<<grid, 256>>>(h4, fw1, part, NB, 2048, 8192, 4096);
        combine_tanh<<<(NB * 2048 + 255) / 256, 256>>>(part, fb1, a1, NB, 2048);
    }
    // fc2: (128,2048) @ (2048,2048) + tanh
    {
        dim3 grid(2048 / 64, NB / 64);
        gemm64v2<1><<<grid, 256>>>(a1, fw2, fb2, a2, NB, 2048, 2048);
    }
    // fc3: (128,2048) @ (2048,62)
    fc_small<<<NB, 64>>>(a2, fw3, fb3, pp, OUTDIM, 2048);

    // trajectory assembly -> (128, 4000, 2)
    traj_kernel<<<NB, 256>>>(pp, dict, out);
}